// round 1
// baseline (speedup 1.0000x reference)
#include <cuda_runtime.h>
#include <math.h>

// Problem constants
#define BB   32
#define NN_  4096
#define PP   256
#define DX_  128
#define DU_  64
#define DK_  128
#define DV_  128
#define DOUT_ 256
#define HH   512
#define TOK  (BB*NN_)   // 131072
#define BPQ  (BB*PP)    // 8192

// ---------------- scratch (static device globals; no allocation) -------------
__device__ float g_h1[(size_t)TOK*HH];       // 256 MB
__device__ float g_h2[(size_t)TOK*HH];       // 256 MB
__device__ float g_Kb[(size_t)TOK*DK_];      // 64 MB
__device__ float g_Vb[(size_t)TOK*DV_];      // 64 MB
__device__ float g_xu[(size_t)TOK*(DX_+DU_)];// 96 MB
__device__ float g_S [(size_t)BB*PP*NN_];    // 134 MB
__device__ float g_Q [(size_t)BPQ*DK_];
__device__ float g_pool[(size_t)BPQ*DV_];
__device__ float g_dQ[(size_t)BPQ*DK_];
__device__ float g_lw[(size_t)BB*NN_];

// ---------------- helpers ----------------------------------------------------
__device__ __forceinline__ float gelu_tanh(float x) {
    float x3 = x*x*x;
    return 0.5f*x*(1.0f + tanhf(0.7978845608028654f*(x + 0.044715f*x3)));
}
__device__ __forceinline__ float warp_sum(float v) {
#pragma unroll
    for (int o = 16; o > 0; o >>= 1) v += __shfl_xor_sync(0xffffffffu, v, o);
    return v;
}
__device__ __forceinline__ float warp_max(float v) {
#pragma unroll
    for (int o = 16; o > 0; o >>= 1) v = fmaxf(v, __shfl_xor_sync(0xffffffffu, v, o));
    return v;
}

// ---------------- generic batched SGEMM (NN): C = epi(A[M,K] @ W[K,N]) -------
// EPI: 0 = none, 1 = +bias, 2 = gelu(+bias)
// 128x128 tile, BK=8, 256 threads, 8x8 per thread.
template<int EPI>
__global__ __launch_bounds__(256)
void gemm_nn(const float* __restrict__ A, const float* __restrict__ W,
             const float* __restrict__ bias, float* __restrict__ C,
             int M, int N, int K,
             size_t sA, size_t sW, size_t sC)
{
    __shared__ float As[8][128];
    __shared__ float Bs[8][128];
    const int tid = threadIdx.x;
    const int bm = blockIdx.y * 128, bn = blockIdx.x * 128;
    A += (size_t)blockIdx.z * sA;
    W += (size_t)blockIdx.z * sW;
    C += (size_t)blockIdx.z * sC;

    const int arow = tid >> 1, acol = (tid & 1) * 4;   // A tile: 128 rows x 8 k
    const int brow = tid >> 5, bcol = (tid & 31) * 4;  // W tile: 8 k x 128 cols
    const int tx = tid & 15, ty = tid >> 4;

    float acc[8][8];
#pragma unroll
    for (int i = 0; i < 8; i++)
#pragma unroll
        for (int j = 0; j < 8; j++) acc[i][j] = 0.f;

    for (int k0 = 0; k0 < K; k0 += 8) {
        float4 a = *(const float4*)(A + (size_t)(bm + arow) * K + k0 + acol);
        float4 b = *(const float4*)(W + (size_t)(k0 + brow) * N + bn + bcol);
        __syncthreads();
        As[acol + 0][arow] = a.x; As[acol + 1][arow] = a.y;
        As[acol + 2][arow] = a.z; As[acol + 3][arow] = a.w;
        *(float4*)&Bs[brow][bcol] = b;
        __syncthreads();
#pragma unroll
        for (int k = 0; k < 8; k++) {
            float4 a0 = *(float4*)&As[k][ty * 8];
            float4 a1 = *(float4*)&As[k][ty * 8 + 4];
            float4 b0 = *(float4*)&Bs[k][tx * 8];
            float4 b1 = *(float4*)&Bs[k][tx * 8 + 4];
            float ar[8] = {a0.x,a0.y,a0.z,a0.w,a1.x,a1.y,a1.z,a1.w};
            float br[8] = {b0.x,b0.y,b0.z,b0.w,b1.x,b1.y,b1.z,b1.w};
#pragma unroll
            for (int i = 0; i < 8; i++)
#pragma unroll
                for (int j = 0; j < 8; j++) acc[i][j] = fmaf(ar[i], br[j], acc[i][j]);
        }
    }

#pragma unroll
    for (int i = 0; i < 8; i++) {
        int row = bm + ty * 8 + i;
        float* c = C + (size_t)row * N + bn + tx * 8;
#pragma unroll
        for (int j = 0; j < 8; j++) {
            float v = acc[i][j];
            if (EPI >= 1) v += bias[bn + tx * 8 + j];
            if (EPI == 2) v = gelu_tanh(v);
            c[j] = v;
        }
    }
}

// ---------------- NT GEMM for scores: S = Q @ K^T * scale + logw -------------
__global__ __launch_bounds__(256)
void gemm_nt_scores(const float* __restrict__ Q, const float* __restrict__ Km,
                    const float* __restrict__ logw, float* __restrict__ S,
                    int M, int N, int K, float scale,
                    size_t sQ, size_t sK, size_t sS, size_t sL)
{
    __shared__ float As[8][128];
    __shared__ float Bs[8][128];
    const int tid = threadIdx.x;
    const int bm = blockIdx.y * 128, bn = blockIdx.x * 128;
    Q  += (size_t)blockIdx.z * sQ;
    Km += (size_t)blockIdx.z * sK;
    S  += (size_t)blockIdx.z * sS;
    logw += (size_t)blockIdx.z * sL;

    const int arow = tid >> 1, acol = (tid & 1) * 4;
    const int tx = tid & 15, ty = tid >> 4;

    float acc[8][8];
#pragma unroll
    for (int i = 0; i < 8; i++)
#pragma unroll
        for (int j = 0; j < 8; j++) acc[i][j] = 0.f;

    for (int k0 = 0; k0 < K; k0 += 8) {
        float4 a = *(const float4*)(Q  + (size_t)(bm + arow) * K + k0 + acol);
        float4 b = *(const float4*)(Km + (size_t)(bn + arow) * K + k0 + acol);
        __syncthreads();
        As[acol + 0][arow] = a.x; As[acol + 1][arow] = a.y;
        As[acol + 2][arow] = a.z; As[acol + 3][arow] = a.w;
        Bs[acol + 0][arow] = b.x; Bs[acol + 1][arow] = b.y;
        Bs[acol + 2][arow] = b.z; Bs[acol + 3][arow] = b.w;
        __syncthreads();
#pragma unroll
        for (int k = 0; k < 8; k++) {
            float4 a0 = *(float4*)&As[k][ty * 8];
            float4 a1 = *(float4*)&As[k][ty * 8 + 4];
            float4 b0 = *(float4*)&Bs[k][tx * 8];
            float4 b1 = *(float4*)&Bs[k][tx * 8 + 4];
            float ar[8] = {a0.x,a0.y,a0.z,a0.w,a1.x,a1.y,a1.z,a1.w};
            float br[8] = {b0.x,b0.y,b0.z,b0.w,b1.x,b1.y,b1.z,b1.w};
#pragma unroll
            for (int i = 0; i < 8; i++)
#pragma unroll
                for (int j = 0; j < 8; j++) acc[i][j] = fmaf(ar[i], br[j], acc[i][j]);
        }
    }

#pragma unroll
    for (int i = 0; i < 8; i++) {
        int row = bm + ty * 8 + i;
        float* c = S + (size_t)row * N + bn + tx * 8;
#pragma unroll
        for (int j = 0; j < 8; j++) {
            c[j] = acc[i][j] * scale + logw[bn + tx * 8 + j];
        }
    }
}

// ---------------- softmax over rows of length 4096 ---------------------------
__global__ __launch_bounds__(256)
void softmax4096(float* __restrict__ S)
{
    float* s = S + (size_t)blockIdx.x * NN_;
    const int t = threadIdx.x;
    const int w = t >> 5, lane = t & 31;
    __shared__ float red[8];

    float v[16];
    float mx = -INFINITY;
#pragma unroll
    for (int i = 0; i < 16; i++) { v[i] = s[t + i * 256]; mx = fmaxf(mx, v[i]); }
    mx = warp_max(mx);
    if (lane == 0) red[w] = mx;
    __syncthreads();
    mx = red[0];
#pragma unroll
    for (int i = 1; i < 8; i++) mx = fmaxf(mx, red[i]);
    __syncthreads();

    float sum = 0.f;
#pragma unroll
    for (int i = 0; i < 16; i++) { v[i] = __expf(v[i] - mx); sum += v[i]; }
    sum = warp_sum(sum);
    if (lane == 0) red[w] = sum;
    __syncthreads();
    float tot = 0.f;
#pragma unroll
    for (int i = 0; i < 8; i++) tot += red[i];
    float inv = 1.0f / tot;
#pragma unroll
    for (int i = 0; i < 16; i++) s[t + i * 256] = v[i] * inv;
}

// ---------------- Q = LayerNorm(Q + dQ) over DK=128 --------------------------
__global__ __launch_bounds__(128)
void add_layernorm(float* __restrict__ Q, const float* __restrict__ dQ,
                   const float* __restrict__ g, const float* __restrict__ b)
{
    const int row = blockIdx.x, t = threadIdx.x;
    const size_t idx = (size_t)row * DK_ + t;
    const int w = t >> 5, lane = t & 31;
    __shared__ float sh[4];

    float x = Q[idx] + dQ[idx];
    float s = warp_sum(x);
    if (lane == 0) sh[w] = s;
    __syncthreads();
    float mean = (sh[0] + sh[1] + sh[2] + sh[3]) * (1.0f / DK_);
    float d = x - mean;
    __syncthreads();
    float s2 = warp_sum(d * d);
    if (lane == 0) sh[w] = s2;
    __syncthreads();
    float var = (sh[0] + sh[1] + sh[2] + sh[3]) * (1.0f / DK_);
    Q[idx] = d * rsqrtf(var + 1e-5f) * g[t] + b[t];
}

// ---------------- prep: masked log-weights (mask dtype auto-detect) ----------
__global__ void prep_logw(const void* __restrict__ mask, const float* __restrict__ sw,
                          float* __restrict__ lw, int n)
{
    const unsigned int w0 = *(const unsigned int*)mask;
    const int mode = (w0 == 0x3F800000u) ? 2 : ((w0 == 1u) ? 1 : 0); // 2=f32,1=i32,0=u8
    int i = blockIdx.x * blockDim.x + threadIdx.x;
    if (i >= n) return;
    bool on;
    if (mode == 1)      on = ((const int*)mask)[i] != 0;
    else if (mode == 2) on = ((const float*)mask)[i] != 0.f;
    else                on = ((const unsigned char*)mask)[i] != 0;
    lw[i] = on ? logf(fmaxf(sw[i], 1e-8f)) : -INFINITY;
}

// ---------------- concat [x_enc | u] -----------------------------------------
__global__ void concat_xu(const float* __restrict__ x, const float* __restrict__ u,
                          float* __restrict__ xu)
{
    const size_t total = (size_t)TOK * (DX_ + DU_);
    for (size_t i = (size_t)blockIdx.x * blockDim.x + threadIdx.x; i < total;
         i += (size_t)gridDim.x * blockDim.x) {
        size_t tkn = i / (DX_ + DU_);
        int c = (int)(i - tkn * (DX_ + DU_));
        xu[i] = (c < DX_) ? x[tkn * DX_ + c] : u[tkn * DU_ + (c - DX_)];
    }
}

// ---------------- broadcast query tokens over batch --------------------------
__global__ void bcast_q(const float* __restrict__ qt, float* __restrict__ Q)
{
    const size_t total = (size_t)BPQ * DK_;
    const size_t per = (size_t)PP * DK_;
    for (size_t i = (size_t)blockIdx.x * blockDim.x + threadIdx.x; i < total;
         i += (size_t)gridDim.x * blockDim.x) {
        Q[i] = qt[i % per];
    }
}

// ---------------- host launcher ----------------------------------------------
static float* sym(const void* p) { return (float*)p; }

extern "C" void kernel_launch(void* const* d_in, const int* in_sizes, int n_in,
                              void* d_out, int out_size)
{
    const float* x_enc = (const float*)d_in[0];
    const float* u     = (const float*)d_in[1];
    const void*  mask  = d_in[2];
    const float* sw    = (const float*)d_in[3];
    const float* k_w1 = (const float*)d_in[4];  const float* k_b1 = (const float*)d_in[5];
    const float* k_w2 = (const float*)d_in[6];  const float* k_b2 = (const float*)d_in[7];
    const float* k_w3 = (const float*)d_in[8];  const float* k_b3 = (const float*)d_in[9];
    const float* v_w1 = (const float*)d_in[10]; const float* v_b1 = (const float*)d_in[11];
    const float* v_w2 = (const float*)d_in[12]; const float* v_b2 = (const float*)d_in[13];
    const float* v_w3 = (const float*)d_in[14]; const float* v_b3 = (const float*)d_in[15];
    const float* qtok = (const float*)d_in[16];
    const float* rho_w1 = (const float*)d_in[17]; const float* rho_b1 = (const float*)d_in[18];
    const float* rho_w2 = (const float*)d_in[19]; const float* rho_b2 = (const float*)d_in[20];
    const float* ref_w1 = (const float*)d_in[21]; const float* ref_b1 = (const float*)d_in[22];
    const float* ref_w2 = (const float*)d_in[23]; const float* ref_b2 = (const float*)d_in[24];
    const float* ln_g = (const float*)d_in[25];   const float* ln_b = (const float*)d_in[26];
    float* out = (float*)d_out;

    float *h1, *h2, *Kb, *Vb, *xu, *S, *Q, *pool, *dQ, *lw;
    cudaGetSymbolAddress((void**)&h1, g_h1);
    cudaGetSymbolAddress((void**)&h2, g_h2);
    cudaGetSymbolAddress((void**)&Kb, g_Kb);
    cudaGetSymbolAddress((void**)&Vb, g_Vb);
    cudaGetSymbolAddress((void**)&xu, g_xu);
    cudaGetSymbolAddress((void**)&S,  g_S);
    cudaGetSymbolAddress((void**)&Q,  g_Q);
    cudaGetSymbolAddress((void**)&pool, g_pool);
    cudaGetSymbolAddress((void**)&dQ, g_dQ);
    cudaGetSymbolAddress((void**)&lw, g_lw);

    const float scale = 0.08838834764831843f; // 1/sqrt(128)

    // prep
    prep_logw<<<(TOK + 255) / 256, 256>>>(mask, sw, lw, TOK);
    concat_xu<<<2048, 256>>>(x_enc, u, xu);
    bcast_q<<<2048, 256>>>(qtok, Q);

    // K = mlp3(x_enc)
    gemm_nn<2><<<dim3(HH / 128, TOK / 128, 1), 256>>>(x_enc, k_w1, k_b1, h1, TOK, HH, DX_, 0, 0, 0);
    gemm_nn<2><<<dim3(HH / 128, TOK / 128, 1), 256>>>(h1, k_w2, k_b2, h2, TOK, HH, HH, 0, 0, 0);
    gemm_nn<1><<<dim3(DK_ / 128, TOK / 128, 1), 256>>>(h2, k_w3, k_b3, Kb, TOK, DK_, HH, 0, 0, 0);

    // V = mlp3([x_enc|u])
    gemm_nn<2><<<dim3(HH / 128, TOK / 128, 1), 256>>>(xu, v_w1, v_b1, h1, TOK, HH, DX_ + DU_, 0, 0, 0);
    gemm_nn<2><<<dim3(HH / 128, TOK / 128, 1), 256>>>(h1, v_w2, v_b2, h2, TOK, HH, HH, 0, 0, 0);
    gemm_nn<1><<<dim3(DV_ / 128, TOK / 128, 1), 256>>>(h2, v_w3, v_b3, Vb, TOK, DV_, HH, 0, 0, 0);

    // attention + refinement
    for (int iter = 0; iter < 3; iter++) {
        gemm_nt_scores<<<dim3(NN_ / 128, PP / 128, BB), 256>>>(
            Q, Kb, lw, S, PP, NN_, DK_, scale,
            (size_t)PP * DK_, (size_t)NN_ * DK_, (size_t)PP * NN_, (size_t)NN_);
        softmax4096<<<BB * PP, 256>>>(S);
        gemm_nn<0><<<dim3(DV_ / 128, PP / 128, BB), 256>>>(
            S, Vb, nullptr, pool, PP, DV_, NN_,
            (size_t)PP * NN_, (size_t)NN_ * DV_, (size_t)PP * DV_);
        if (iter < 2) {
            gemm_nn<2><<<dim3(HH / 128, BPQ / 128, 1), 256>>>(pool, ref_w1, ref_b1, h1, BPQ, HH, DV_, 0, 0, 0);
            gemm_nn<1><<<dim3(DK_ / 128, BPQ / 128, 1), 256>>>(h1, ref_w2, ref_b2, dQ, BPQ, DK_, HH, 0, 0, 0);
            add_layernorm<<<BPQ, 128>>>(Q, dQ, ln_g, ln_b);
        }
    }

    // out = mlp2(pooled)
    gemm_nn<2><<<dim3(HH / 128, BPQ / 128, 1), 256>>>(pool, rho_w1, rho_b1, h1, BPQ, HH, DV_, 0, 0, 0);
    gemm_nn<1><<<dim3(DOUT_ / 128, BPQ / 128, 1), 256>>>(h1, rho_w2, rho_b2, out, BPQ, DOUT_, HH, 0, 0, 0);

    (void)in_sizes; (void)n_in; (void)out_size; (void)sym;
}

// round 2
// speedup vs baseline: 1.0415x; 1.0415x over previous
#include <cuda_runtime.h>
#include <math.h>

// Problem constants
#define BB   32
#define NN_  4096
#define PP   256
#define DX_  128
#define DU_  64
#define DK_  128
#define DV_  128
#define DOUT_ 256
#define HH   512
#define TOK  (BB*NN_)   // 131072
#define BPQ  (BB*PP)    // 8192
#define KSPLIT 8        // split-K factor for the A*V GEMM (K=4096 -> 8x512)

// ---------------- scratch (static device globals; no allocation) -------------
__device__ float g_h1[(size_t)TOK*HH];       // 256 MB
__device__ float g_h2[(size_t)TOK*HH];       // 256 MB (also reused for AV split-K partials)
__device__ float g_Kb[(size_t)TOK*DK_];      // 64 MB
__device__ float g_Vb[(size_t)TOK*DV_];      // 64 MB
__device__ float g_xu[(size_t)TOK*(DX_+DU_)];// 96 MB
__device__ float g_S [(size_t)BB*PP*NN_];    // 134 MB
__device__ float g_Q [(size_t)BPQ*DK_];
__device__ float g_pool[(size_t)BPQ*DV_];
__device__ float g_dQ[(size_t)BPQ*DK_];
__device__ float g_lw[(size_t)BB*NN_];

// ---------------- helpers ----------------------------------------------------
__device__ __forceinline__ float gelu_tanh(float x) {
    float x3 = x*x*x;
    return 0.5f*x*(1.0f + tanhf(0.7978845608028654f*(x + 0.044715f*x3)));
}
__device__ __forceinline__ float warp_sum(float v) {
#pragma unroll
    for (int o = 16; o > 0; o >>= 1) v += __shfl_xor_sync(0xffffffffu, v, o);
    return v;
}
__device__ __forceinline__ float warp_max(float v) {
#pragma unroll
    for (int o = 16; o > 0; o >>= 1) v = fmaxf(v, __shfl_xor_sync(0xffffffffu, v, o));
    return v;
}

// =============================================================================
// Core 128x128 GEMM tile, BK=16, 256 threads, 8x8 per thread,
// double-buffered SMEM, single __syncthreads per k-tile.
// TRB=false: C += A[M,K] @ B[K,N]   (lda = row stride of A, ldb = row stride of B)
// TRB=true : C += A[M,K] @ B[N,K]^T (B stored row-major [N,K], ldb = its row stride)
// =============================================================================
template<bool TRB>
__device__ __forceinline__ void gemm_core(
    const float* __restrict__ A, int lda,
    const float* __restrict__ B, int ldb,
    int K, int bm, int bn, float acc[8][8],
    float As[2][16][128], float Bs[2][16][128])
{
    const int tid = threadIdx.x;
    const int ar = tid >> 1, ac = (tid & 1) * 8;     // A (and TRB-B) load map
    const int br = tid >> 5, bc = (tid & 31) * 4;    // NN-B load map
    const int tx = tid & 15, ty = tid >> 4;

    float4 pa0, pa1, pb0, pb1;

    auto load_tile = [&](int k0) {
        const float* ap = A + (size_t)(bm + ar) * lda + k0 + ac;
        pa0 = *(const float4*)(ap);
        pa1 = *(const float4*)(ap + 4);
        if (TRB) {
            const float* bp = B + (size_t)(bn + ar) * ldb + k0 + ac;
            pb0 = *(const float4*)(bp);
            pb1 = *(const float4*)(bp + 4);
        } else {
            pb0 = *(const float4*)(B + (size_t)(k0 + br) * ldb + bn + bc);
            pb1 = *(const float4*)(B + (size_t)(k0 + br + 8) * ldb + bn + bc);
        }
    };
    auto store_tile = [&](int buf) {
        As[buf][ac + 0][ar] = pa0.x; As[buf][ac + 1][ar] = pa0.y;
        As[buf][ac + 2][ar] = pa0.z; As[buf][ac + 3][ar] = pa0.w;
        As[buf][ac + 4][ar] = pa1.x; As[buf][ac + 5][ar] = pa1.y;
        As[buf][ac + 6][ar] = pa1.z; As[buf][ac + 7][ar] = pa1.w;
        if (TRB) {
            Bs[buf][ac + 0][ar] = pb0.x; Bs[buf][ac + 1][ar] = pb0.y;
            Bs[buf][ac + 2][ar] = pb0.z; Bs[buf][ac + 3][ar] = pb0.w;
            Bs[buf][ac + 4][ar] = pb1.x; Bs[buf][ac + 5][ar] = pb1.y;
            Bs[buf][ac + 6][ar] = pb1.z; Bs[buf][ac + 7][ar] = pb1.w;
        } else {
            *(float4*)&Bs[buf][br][bc]     = pb0;
            *(float4*)&Bs[buf][br + 8][bc] = pb1;
        }
    };

    const int nt = K >> 4;
    load_tile(0);
    store_tile(0);
    __syncthreads();

    for (int t = 0; t < nt; t++) {
        const int buf = t & 1;
        if (t + 1 < nt) load_tile((t + 1) << 4);
#pragma unroll
        for (int k = 0; k < 16; k++) {
            float4 a0 = *(const float4*)&As[buf][k][ty * 8];
            float4 a1 = *(const float4*)&As[buf][k][ty * 8 + 4];
            float4 b0 = *(const float4*)&Bs[buf][k][tx * 8];
            float4 b1 = *(const float4*)&Bs[buf][k][tx * 8 + 4];
            float ar8[8] = {a0.x,a0.y,a0.z,a0.w,a1.x,a1.y,a1.z,a1.w};
            float br8[8] = {b0.x,b0.y,b0.z,b0.w,b1.x,b1.y,b1.z,b1.w};
#pragma unroll
            for (int i = 0; i < 8; i++)
#pragma unroll
                for (int j = 0; j < 8; j++)
                    acc[i][j] = fmaf(ar8[i], br8[j], acc[i][j]);
        }
        if (t + 1 < nt) {
            store_tile(buf ^ 1);
            __syncthreads();
        }
    }
}

// EPI: 0 none, 1 +bias, 2 gelu(+bias), 3 *scale + logw (aux per-z with stride sAux)
template<int EPI, bool TRB>
__global__ __launch_bounds__(256)
void gemm_std(const float* __restrict__ A, const float* __restrict__ B,
              const float* __restrict__ aux, float* __restrict__ C,
              int N, int K, float scale,
              size_t sA, size_t sB, size_t sC, size_t sAux)
{
    __shared__ float As[2][16][128];
    __shared__ float Bs[2][16][128];
    const int bm = blockIdx.y * 128, bn = blockIdx.x * 128;
    const int z = blockIdx.z;

    float acc[8][8];
#pragma unroll
    for (int i = 0; i < 8; i++)
#pragma unroll
        for (int j = 0; j < 8; j++) acc[i][j] = 0.f;

    gemm_core<TRB>(A + (size_t)z * sA, K,
                   B + (size_t)z * sB, TRB ? K : N,
                   K, bm, bn, acc, As, Bs);

    const int tid = threadIdx.x;
    const int tx = tid & 15, ty = tid >> 4;
    const float* ax = (EPI > 0) ? aux + (size_t)z * sAux + bn + tx * 8 : nullptr;
    float* Cz = C + (size_t)z * sC;
#pragma unroll
    for (int i = 0; i < 8; i++) {
        int row = bm + ty * 8 + i;
        float* c = Cz + (size_t)row * N + bn + tx * 8;
#pragma unroll
        for (int j = 0; j < 8; j++) {
            float v = acc[i][j];
            if (EPI == 1) v += ax[j];
            if (EPI == 2) v = gelu_tanh(v + ax[j]);
            if (EPI == 3) v = v * scale + ax[j];
            c[j] = v;
        }
    }
}

// ---------------- split-K GEMM for pooled = A @ V ----------------------------
// grid (1, PP/128, BB*KSPLIT). Writes partials[bz][128*...]; reduced after.
__global__ __launch_bounds__(256)
void gemm_avk(const float* __restrict__ S, const float* __restrict__ V,
              float* __restrict__ Pt)
{
    __shared__ float As[2][16][128];
    __shared__ float Bs[2][16][128];
    const int bz = blockIdx.z;
    const int b = bz >> 3, kc = bz & (KSPLIT - 1);
    const int KC = NN_ / KSPLIT; // 512
    const float* A = S + (size_t)b * PP * NN_ + (size_t)kc * KC;
    const float* Bm = V + (size_t)b * NN_ * DV_ + (size_t)kc * KC * DV_;
    const int bm = blockIdx.y * 128;

    float acc[8][8];
#pragma unroll
    for (int i = 0; i < 8; i++)
#pragma unroll
        for (int j = 0; j < 8; j++) acc[i][j] = 0.f;

    gemm_core<false>(A, NN_, Bm, DV_, KC, bm, 0, acc, As, Bs);

    const int tid = threadIdx.x;
    const int tx = tid & 15, ty = tid >> 4;
    float* c0 = Pt + (size_t)bz * PP * DV_;
#pragma unroll
    for (int i = 0; i < 8; i++) {
        int row = bm + ty * 8 + i;
        float* c = c0 + (size_t)row * DV_ + tx * 8;
#pragma unroll
        for (int j = 0; j < 8; j++) c[j] = acc[i][j];
    }
}

__global__ __launch_bounds__(256)
void reduce_avk(const float* __restrict__ Pt, float* __restrict__ pool)
{
    const size_t total = (size_t)BB * PP * DV_;
    size_t i = (size_t)blockIdx.x * 256 + threadIdx.x;
    if (i >= total) return;
    size_t b = i / ((size_t)PP * DV_);
    size_t r = i - b * (size_t)PP * DV_;
    const float* p = Pt + b * KSPLIT * (size_t)PP * DV_ + r;
    float s = 0.f;
#pragma unroll
    for (int kc = 0; kc < KSPLIT; kc++) s += p[(size_t)kc * PP * DV_];
    pool[i] = s;
}

// ---------------- softmax over rows of length 4096 ---------------------------
__global__ __launch_bounds__(256)
void softmax4096(float* __restrict__ S)
{
    float* s = S + (size_t)blockIdx.x * NN_;
    const int t = threadIdx.x;
    const int w = t >> 5, lane = t & 31;
    __shared__ float red[8];

    float v[16];
    float mx = -INFINITY;
#pragma unroll
    for (int i = 0; i < 16; i++) { v[i] = s[t + i * 256]; mx = fmaxf(mx, v[i]); }
    mx = warp_max(mx);
    if (lane == 0) red[w] = mx;
    __syncthreads();
    mx = red[0];
#pragma unroll
    for (int i = 1; i < 8; i++) mx = fmaxf(mx, red[i]);
    __syncthreads();

    float sum = 0.f;
#pragma unroll
    for (int i = 0; i < 16; i++) { v[i] = __expf(v[i] - mx); sum += v[i]; }
    sum = warp_sum(sum);
    if (lane == 0) red[w] = sum;
    __syncthreads();
    float tot = 0.f;
#pragma unroll
    for (int i = 0; i < 8; i++) tot += red[i];
    float inv = 1.0f / tot;
#pragma unroll
    for (int i = 0; i < 16; i++) s[t + i * 256] = v[i] * inv;
}

// ---------------- Q = LayerNorm(Q + dQ) over DK=128 --------------------------
__global__ __launch_bounds__(128)
void add_layernorm(float* __restrict__ Q, const float* __restrict__ dQ,
                   const float* __restrict__ g, const float* __restrict__ b)
{
    const int row = blockIdx.x, t = threadIdx.x;
    const size_t idx = (size_t)row * DK_ + t;
    const int w = t >> 5, lane = t & 31;
    __shared__ float sh[4];

    float x = Q[idx] + dQ[idx];
    float s = warp_sum(x);
    if (lane == 0) sh[w] = s;
    __syncthreads();
    float mean = (sh[0] + sh[1] + sh[2] + sh[3]) * (1.0f / DK_);
    float d = x - mean;
    __syncthreads();
    float s2 = warp_sum(d * d);
    if (lane == 0) sh[w] = s2;
    __syncthreads();
    float var = (sh[0] + sh[1] + sh[2] + sh[3]) * (1.0f / DK_);
    Q[idx] = d * rsqrtf(var + 1e-5f) * g[t] + b[t];
}

// ---------------- prep: masked log-weights (mask dtype auto-detect) ----------
__global__ void prep_logw(const void* __restrict__ mask, const float* __restrict__ sw,
                          float* __restrict__ lw, int n)
{
    const unsigned int w0 = *(const unsigned int*)mask;
    const int mode = (w0 == 0x3F800000u) ? 2 : ((w0 == 1u) ? 1 : 0); // 2=f32,1=i32,0=u8
    int i = blockIdx.x * blockDim.x + threadIdx.x;
    if (i >= n) return;
    bool on;
    if (mode == 1)      on = ((const int*)mask)[i] != 0;
    else if (mode == 2) on = ((const float*)mask)[i] != 0.f;
    else                on = ((const unsigned char*)mask)[i] != 0;
    lw[i] = on ? logf(fmaxf(sw[i], 1e-8f)) : -INFINITY;
}

// ---------------- concat [x_enc | u] -----------------------------------------
__global__ void concat_xu(const float* __restrict__ x, const float* __restrict__ u,
                          float* __restrict__ xu)
{
    const size_t total = (size_t)TOK * (DX_ + DU_);
    for (size_t i = (size_t)blockIdx.x * blockDim.x + threadIdx.x; i < total;
         i += (size_t)gridDim.x * blockDim.x) {
        size_t tkn = i / (DX_ + DU_);
        int c = (int)(i - tkn * (DX_ + DU_));
        xu[i] = (c < DX_) ? x[tkn * DX_ + c] : u[tkn * DU_ + (c - DX_)];
    }
}

// ---------------- broadcast query tokens over batch --------------------------
__global__ void bcast_q(const float* __restrict__ qt, float* __restrict__ Q)
{
    const size_t total = (size_t)BPQ * DK_;
    const size_t per = (size_t)PP * DK_;
    for (size_t i = (size_t)blockIdx.x * blockDim.x + threadIdx.x; i < total;
         i += (size_t)gridDim.x * blockDim.x) {
        Q[i] = qt[i % per];
    }
}

// ---------------- host launcher ----------------------------------------------
extern "C" void kernel_launch(void* const* d_in, const int* in_sizes, int n_in,
                              void* d_out, int out_size)
{
    const float* x_enc = (const float*)d_in[0];
    const float* u     = (const float*)d_in[1];
    const void*  mask  = d_in[2];
    const float* sw    = (const float*)d_in[3];
    const float* k_w1 = (const float*)d_in[4];  const float* k_b1 = (const float*)d_in[5];
    const float* k_w2 = (const float*)d_in[6];  const float* k_b2 = (const float*)d_in[7];
    const float* k_w3 = (const float*)d_in[8];  const float* k_b3 = (const float*)d_in[9];
    const float* v_w1 = (const float*)d_in[10]; const float* v_b1 = (const float*)d_in[11];
    const float* v_w2 = (const float*)d_in[12]; const float* v_b2 = (const float*)d_in[13];
    const float* v_w3 = (const float*)d_in[14]; const float* v_b3 = (const float*)d_in[15];
    const float* qtok = (const float*)d_in[16];
    const float* rho_w1 = (const float*)d_in[17]; const float* rho_b1 = (const float*)d_in[18];
    const float* rho_w2 = (const float*)d_in[19]; const float* rho_b2 = (const float*)d_in[20];
    const float* ref_w1 = (const float*)d_in[21]; const float* ref_b1 = (const float*)d_in[22];
    const float* ref_w2 = (const float*)d_in[23]; const float* ref_b2 = (const float*)d_in[24];
    const float* ln_g = (const float*)d_in[25];   const float* ln_b = (const float*)d_in[26];
    float* out = (float*)d_out;

    float *h1, *h2, *Kb, *Vb, *xu, *S, *Q, *pool, *dQ, *lw;
    cudaGetSymbolAddress((void**)&h1, g_h1);
    cudaGetSymbolAddress((void**)&h2, g_h2);
    cudaGetSymbolAddress((void**)&Kb, g_Kb);
    cudaGetSymbolAddress((void**)&Vb, g_Vb);
    cudaGetSymbolAddress((void**)&xu, g_xu);
    cudaGetSymbolAddress((void**)&S,  g_S);
    cudaGetSymbolAddress((void**)&Q,  g_Q);
    cudaGetSymbolAddress((void**)&pool, g_pool);
    cudaGetSymbolAddress((void**)&dQ, g_dQ);
    cudaGetSymbolAddress((void**)&lw, g_lw);

    const float scale = 0.08838834764831843f; // 1/sqrt(128)

    // prep
    prep_logw<<<(TOK + 255) / 256, 256>>>(mask, sw, lw, TOK);
    concat_xu<<<2048, 256>>>(x_enc, u, xu);
    bcast_q<<<2048, 256>>>(qtok, Q);

    // K = mlp3(x_enc):  (TOK,128)->512->512->128
    gemm_std<2,false><<<dim3(HH/128, TOK/128, 1), 256>>>(x_enc, k_w1, k_b1, h1, HH, DX_, 0.f, 0,0,0,0);
    gemm_std<2,false><<<dim3(HH/128, TOK/128, 1), 256>>>(h1, k_w2, k_b2, h2, HH, HH, 0.f, 0,0,0,0);
    gemm_std<1,false><<<dim3(DK_/128, TOK/128, 1), 256>>>(h2, k_w3, k_b3, Kb, DK_, HH, 0.f, 0,0,0,0);

    // V = mlp3([x_enc|u]): (TOK,192)->512->512->128
    gemm_std<2,false><<<dim3(HH/128, TOK/128, 1), 256>>>(xu, v_w1, v_b1, h1, HH, DX_+DU_, 0.f, 0,0,0,0);
    gemm_std<2,false><<<dim3(HH/128, TOK/128, 1), 256>>>(h1, v_w2, v_b2, h2, HH, HH, 0.f, 0,0,0,0);
    gemm_std<1,false><<<dim3(DV_/128, TOK/128, 1), 256>>>(h2, v_w3, v_b3, Vb, DV_, HH, 0.f, 0,0,0,0);

    // attention + refinement (3 iterations)
    for (int iter = 0; iter < 3; iter++) {
        // scores = Q @ K^T * scale + logw   [per batch: 256 x 4096]
        gemm_std<3,true><<<dim3(NN_/128, PP/128, BB), 256>>>(
            Q, Kb, lw, S, NN_, DK_, scale,
            (size_t)PP*DK_, (size_t)NN_*DK_, (size_t)PP*NN_, (size_t)NN_);
        softmax4096<<<BB*PP, 256>>>(S);
        // pooled = A @ V  via split-K (partials into g_h2 scratch)
        gemm_avk<<<dim3(1, PP/128, BB*KSPLIT), 256>>>(S, Vb, h2);
        reduce_avk<<<(BB*PP*DV_ + 255)/256, 256>>>(h2, pool);
        if (iter < 2) {
            gemm_std<2,false><<<dim3(HH/128, BPQ/128, 1), 256>>>(pool, ref_w1, ref_b1, h1, HH, DV_, 0.f, 0,0,0,0);
            gemm_std<1,false><<<dim3(DK_/128, BPQ/128, 1), 256>>>(h1, ref_w2, ref_b2, dQ, DK_, HH, 0.f, 0,0,0,0);
            add_layernorm<<<BPQ, 128>>>(Q, dQ, ln_g, ln_b);
        }
    }

    // out = mlp2(pooled): (8192,128)->512->256
    gemm_std<2,false><<<dim3(HH/128, BPQ/128, 1), 256>>>(pool, rho_w1, rho_b1, h1, HH, DV_, 0.f, 0,0,0,0);
    gemm_std<1,false><<<dim3(DOUT_/128, BPQ/128, 1), 256>>>(h1, rho_w2, rho_b2, out, DOUT_, HH, 0.f, 0,0,0,0);

    (void)in_sizes; (void)n_in; (void)out_size;
}

// round 3
// speedup vs baseline: 1.5760x; 1.5132x over previous
#include <cuda_runtime.h>
#include <math.h>

// Problem constants
#define BB   32
#define NN_  4096
#define PP   256
#define DX_  128
#define DU_  64
#define DK_  128
#define DV_  128
#define DOUT_ 256
#define HH   512
#define TOK  (BB*NN_)   // 131072
#define BPQ  (BB*PP)    // 8192
#define KSPLIT 8        // split-K factor for the A*V GEMM (K=4096 -> 8x512)

// ---------------- scratch (static device globals; no allocation) -------------
__device__ float g_h1[(size_t)TOK*HH];       // 256 MB
__device__ float g_h2[(size_t)TOK*HH];       // 256 MB (also AV split-K partials)
__device__ float g_Kb[(size_t)TOK*DK_];
__device__ float g_Vb[(size_t)TOK*DV_];
__device__ float g_xu[(size_t)TOK*(DX_+DU_)];
__device__ float g_S [(size_t)BB*PP*NN_];
__device__ float g_Q [(size_t)BPQ*DK_];
__device__ float g_pool[(size_t)BPQ*DV_];
__device__ float g_dQ[(size_t)BPQ*DK_];
__device__ float g_lw[(size_t)BB*NN_];

// ---------------- helpers ----------------------------------------------------
__device__ __forceinline__ float gelu_tanh(float x) {
    float x3 = x*x*x;
    return 0.5f*x*(1.0f + tanhf(0.7978845608028654f*(x + 0.044715f*x3)));
}
__device__ __forceinline__ float warp_sum(float v) {
#pragma unroll
    for (int o = 16; o > 0; o >>= 1) v += __shfl_xor_sync(0xffffffffu, v, o);
    return v;
}
__device__ __forceinline__ float warp_max(float v) {
#pragma unroll
    for (int o = 16; o > 0; o >>= 1) v = fmaxf(v, __shfl_xor_sync(0xffffffffu, v, o));
    return v;
}

// ---------------- tensor-core primitives -------------------------------------
__device__ __forceinline__ void mma_tf32(float d[4], const unsigned a[4], const unsigned b[2]) {
    asm volatile(
        "mma.sync.aligned.m16n8k8.row.col.f32.tf32.tf32.f32 "
        "{%0,%1,%2,%3}, {%4,%5,%6,%7}, {%8,%9}, {%0,%1,%2,%3};\n"
        : "+f"(d[0]), "+f"(d[1]), "+f"(d[2]), "+f"(d[3])
        : "r"(a[0]), "r"(a[1]), "r"(a[2]), "r"(a[3]), "r"(b[0]), "r"(b[1]));
}
// split x (fp32) into tf32 hi + tf32 lo, x ~= hi + lo (error ~2^-22 * |x|)
__device__ __forceinline__ void split_tf32(float x, unsigned &hi, unsigned &lo) {
    unsigned h;
    asm("cvt.rna.tf32.f32 %0, %1;" : "=r"(h) : "f"(x));
    float r = x - __uint_as_float(h);
    unsigned l;
    asm("cvt.rna.tf32.f32 %0, %1;" : "=r"(l) : "f"(r));
    hi = h; lo = l;
}
__device__ __forceinline__ unsigned smem_u32(const void* p) {
    return (unsigned)__cvta_generic_to_shared(p);
}
__device__ __forceinline__ void cp16(unsigned dst, const void* src) {
    asm volatile("cp.async.cg.shared.global [%0], [%1], 16;\n" :: "r"(dst), "l"(src));
}

template<bool TRB> struct BDim;
template<> struct BDim<false> { static constexpr int R = 16;  static constexpr int C = 136; };
template<> struct BDim<true>  { static constexpr int R = 128; static constexpr int C = 20;  };

// =============================================================================
// 3xTF32 tensor-core GEMM core. 128x128 block tile, BK=16, 256 threads.
// Warp grid 2(m) x 4(n): each warp 64x32 via m16n8k8 tiles.
// TRB=false: C += A[.,K](lda) @ B[K,N](ldb)
// TRB=true : C += A[.,K](lda) @ B[N,K](ldb)^T
// smem strides chosen conflict-free: As stride 20 (banks 20g+t4 all distinct),
// Bs NN stride 136 (8*t4+g distinct), TRB stride 20. All 16B-aligned rows.
// =============================================================================
template<bool TRB>
__device__ __forceinline__ void tc_core(
    const float* __restrict__ Ag, int lda,
    const float* __restrict__ Bg, int ldb,
    int K, int bm, int bn,
    float (&acc)[4][4][4],
    float (&As)[2][128][20],
    float (&Bs)[2][BDim<TRB>::R][BDim<TRB>::C])
{
    const int tid = threadIdx.x;
    const int lane = tid & 31;
    const int g = lane >> 2, t4 = lane & 3;
    const int warp = tid >> 5;
    const int m0 = (warp >> 2) * 64, n0 = (warp & 3) * 32;

    auto issue = [&](int k0, int buf) {
#pragma unroll
        for (int i = 0; i < 2; i++) {
            int c = tid + i * 256;
            int r = c >> 2, q = (c & 3) * 4;
            cp16(smem_u32(&As[buf][r][q]), Ag + (size_t)(bm + r) * lda + k0 + q);
        }
#pragma unroll
        for (int i = 0; i < 2; i++) {
            int c = tid + i * 256;
            if (TRB) {
                int r = c >> 2, q = (c & 3) * 4;
                cp16(smem_u32(&Bs[buf][r][q]), Bg + (size_t)(bn + r) * ldb + k0 + q);
            } else {
                int r = c >> 5, q = (c & 31) * 4;
                cp16(smem_u32(&Bs[buf][r][q]), Bg + (size_t)(k0 + r) * ldb + bn + q);
            }
        }
        asm volatile("cp.async.commit_group;\n");
    };

    const int nt = K >> 4;
    issue(0, 0);
    for (int t = 0; t < nt; t++) {
        const int buf = t & 1;
        if (t + 1 < nt) {
            issue((t + 1) << 4, buf ^ 1);
            asm volatile("cp.async.wait_group 1;\n");
        } else {
            asm volatile("cp.async.wait_group 0;\n");
        }
        __syncthreads();
#pragma unroll
        for (int kk = 0; kk < 16; kk += 8) {
            unsigned ah[4][4], al[4][4], bh[4][2], bl[4][2];
#pragma unroll
            for (int mi = 0; mi < 4; mi++) {
                int mr = m0 + mi * 16;
                split_tf32(As[buf][mr + g    ][kk + t4    ], ah[mi][0], al[mi][0]);
                split_tf32(As[buf][mr + g + 8][kk + t4    ], ah[mi][1], al[mi][1]);
                split_tf32(As[buf][mr + g    ][kk + t4 + 4], ah[mi][2], al[mi][2]);
                split_tf32(As[buf][mr + g + 8][kk + t4 + 4], ah[mi][3], al[mi][3]);
            }
#pragma unroll
            for (int ni = 0; ni < 4; ni++) {
                float b0, b1;
                if (TRB) {
                    b0 = Bs[buf][n0 + ni * 8 + g][kk + t4];
                    b1 = Bs[buf][n0 + ni * 8 + g][kk + t4 + 4];
                } else {
                    b0 = Bs[buf][kk + t4    ][n0 + ni * 8 + g];
                    b1 = Bs[buf][kk + t4 + 4][n0 + ni * 8 + g];
                }
                split_tf32(b0, bh[ni][0], bl[ni][0]);
                split_tf32(b1, bh[ni][1], bl[ni][1]);
            }
#pragma unroll
            for (int mi = 0; mi < 4; mi++)
#pragma unroll
                for (int ni = 0; ni < 4; ni++) {
                    mma_tf32(acc[mi][ni], al[mi], bh[ni]);  // lo*hi
                    mma_tf32(acc[mi][ni], ah[mi], bl[ni]);  // hi*lo
                    mma_tf32(acc[mi][ni], ah[mi], bh[ni]);  // hi*hi
                }
        }
        __syncthreads();
    }
}

// EPI: 0 none, 1 +bias, 2 gelu(+bias), 3 *scale + logw(per-z, stride sAux)
template<int EPI, bool TRB>
__global__ __launch_bounds__(256)
void gemm_tc(const float* __restrict__ A, const float* __restrict__ B,
             const float* __restrict__ aux, float* __restrict__ C,
             int N, int K, float scale,
             size_t sA, size_t sB, size_t sC, size_t sAux)
{
    __shared__ float As[2][128][20];
    __shared__ float Bs[2][BDim<TRB>::R][BDim<TRB>::C];
    const int bm = blockIdx.y * 128, bn = blockIdx.x * 128, z = blockIdx.z;

    float acc[4][4][4];
#pragma unroll
    for (int a = 0; a < 4; a++)
#pragma unroll
        for (int b = 0; b < 4; b++)
#pragma unroll
            for (int c = 0; c < 4; c++) acc[a][b][c] = 0.f;

    tc_core<TRB>(A + (size_t)z * sA, K, B + (size_t)z * sB, TRB ? K : N,
                 K, bm, bn, acc, As, Bs);

    const int tid = threadIdx.x, lane = tid & 31, warp = tid >> 5;
    const int g = lane >> 2, t4 = lane & 3;
    const int m0 = (warp >> 2) * 64, n0 = (warp & 3) * 32;
    float* Cz = C + (size_t)z * sC;
    const float* ax = (EPI > 0) ? aux + (size_t)z * sAux : nullptr;
#pragma unroll
    for (int mi = 0; mi < 4; mi++) {
#pragma unroll
        for (int ni = 0; ni < 4; ni++) {
            int col = bn + n0 + ni * 8 + 2 * t4;
#pragma unroll
            for (int h = 0; h < 2; h++) {
                int row = bm + m0 + mi * 16 + g + h * 8;
                float v0 = acc[mi][ni][2 * h], v1 = acc[mi][ni][2 * h + 1];
                if (EPI == 1) { v0 += ax[col]; v1 += ax[col + 1]; }
                if (EPI == 2) { v0 = gelu_tanh(v0 + ax[col]); v1 = gelu_tanh(v1 + ax[col + 1]); }
                if (EPI == 3) { v0 = v0 * scale + ax[col]; v1 = v1 * scale + ax[col + 1]; }
                *(float2*)(Cz + (size_t)row * N + col) = make_float2(v0, v1);
            }
        }
    }
}

// ---------------- split-K tensor GEMM for pooled = A @ V ---------------------
__global__ __launch_bounds__(256)
void gemm_avk_tc(const float* __restrict__ S, const float* __restrict__ V,
                 float* __restrict__ Pt)
{
    __shared__ float As[2][128][20];
    __shared__ float Bs[2][16][136];
    const int bz = blockIdx.z;
    const int b = bz >> 3, kc = bz & (KSPLIT - 1);
    const int KC = NN_ / KSPLIT; // 512
    const float* A  = S + (size_t)b * PP * NN_ + (size_t)kc * KC;
    const float* Bm = V + (size_t)b * NN_ * DV_ + (size_t)kc * KC * DV_;
    const int bm = blockIdx.y * 128;

    float acc[4][4][4];
#pragma unroll
    for (int a = 0; a < 4; a++)
#pragma unroll
        for (int bb = 0; bb < 4; bb++)
#pragma unroll
            for (int c = 0; c < 4; c++) acc[a][bb][c] = 0.f;

    tc_core<false>(A, NN_, Bm, DV_, KC, bm, 0, acc, As, Bs);

    const int tid = threadIdx.x, lane = tid & 31, warp = tid >> 5;
    const int g = lane >> 2, t4 = lane & 3;
    const int m0 = (warp >> 2) * 64, n0 = (warp & 3) * 32;
    float* c0 = Pt + (size_t)bz * PP * DV_;
#pragma unroll
    for (int mi = 0; mi < 4; mi++)
#pragma unroll
        for (int ni = 0; ni < 4; ni++) {
            int col = n0 + ni * 8 + 2 * t4;
#pragma unroll
            for (int h = 0; h < 2; h++) {
                int row = bm + m0 + mi * 16 + g + h * 8;
                *(float2*)(c0 + (size_t)row * DV_ + col) =
                    make_float2(acc[mi][ni][2 * h], acc[mi][ni][2 * h + 1]);
            }
        }
}

__global__ __launch_bounds__(256)
void reduce_avk(const float* __restrict__ Pt, float* __restrict__ pool)
{
    const size_t total = (size_t)BB * PP * DV_;
    size_t i = (size_t)blockIdx.x * 256 + threadIdx.x;
    if (i >= total) return;
    size_t b = i / ((size_t)PP * DV_);
    size_t r = i - b * (size_t)PP * DV_;
    const float* p = Pt + b * KSPLIT * (size_t)PP * DV_ + r;
    float s = 0.f;
#pragma unroll
    for (int kc = 0; kc < KSPLIT; kc++) s += p[(size_t)kc * PP * DV_];
    pool[i] = s;
}

// ---------------- softmax over rows of length 4096 ---------------------------
__global__ __launch_bounds__(256)
void softmax4096(float* __restrict__ S)
{
    float* s = S + (size_t)blockIdx.x * NN_;
    const int t = threadIdx.x;
    const int w = t >> 5, lane = t & 31;
    __shared__ float red[8];

    float v[16];
    float mx = -INFINITY;
#pragma unroll
    for (int i = 0; i < 16; i++) { v[i] = s[t + i * 256]; mx = fmaxf(mx, v[i]); }
    mx = warp_max(mx);
    if (lane == 0) red[w] = mx;
    __syncthreads();
    mx = red[0];
#pragma unroll
    for (int i = 1; i < 8; i++) mx = fmaxf(mx, red[i]);
    __syncthreads();

    float sum = 0.f;
#pragma unroll
    for (int i = 0; i < 16; i++) { v[i] = __expf(v[i] - mx); sum += v[i]; }
    sum = warp_sum(sum);
    if (lane == 0) red[w] = sum;
    __syncthreads();
    float tot = 0.f;
#pragma unroll
    for (int i = 0; i < 8; i++) tot += red[i];
    float inv = 1.0f / tot;
#pragma unroll
    for (int i = 0; i < 16; i++) s[t + i * 256] = v[i] * inv;
}

// ---------------- Q = LayerNorm(Q + dQ) over DK=128 --------------------------
__global__ __launch_bounds__(128)
void add_layernorm(float* __restrict__ Q, const float* __restrict__ dQ,
                   const float* __restrict__ g, const float* __restrict__ b)
{
    const int row = blockIdx.x, t = threadIdx.x;
    const size_t idx = (size_t)row * DK_ + t;
    const int w = t >> 5, lane = t & 31;
    __shared__ float sh[4];

    float x = Q[idx] + dQ[idx];
    float s = warp_sum(x);
    if (lane == 0) sh[w] = s;
    __syncthreads();
    float mean = (sh[0] + sh[1] + sh[2] + sh[3]) * (1.0f / DK_);
    float d = x - mean;
    __syncthreads();
    float s2 = warp_sum(d * d);
    if (lane == 0) sh[w] = s2;
    __syncthreads();
    float var = (sh[0] + sh[1] + sh[2] + sh[3]) * (1.0f / DK_);
    Q[idx] = d * rsqrtf(var + 1e-5f) * g[t] + b[t];
}

// ---------------- prep: masked log-weights (mask dtype auto-detect) ----------
__global__ void prep_logw(const void* __restrict__ mask, const float* __restrict__ sw,
                          float* __restrict__ lw, int n)
{
    const unsigned int w0 = *(const unsigned int*)mask;
    const int mode = (w0 == 0x3F800000u) ? 2 : ((w0 == 1u) ? 1 : 0); // 2=f32,1=i32,0=u8
    int i = blockIdx.x * blockDim.x + threadIdx.x;
    if (i >= n) return;
    bool on;
    if (mode == 1)      on = ((const int*)mask)[i] != 0;
    else if (mode == 2) on = ((const float*)mask)[i] != 0.f;
    else                on = ((const unsigned char*)mask)[i] != 0;
    lw[i] = on ? logf(fmaxf(sw[i], 1e-8f)) : -INFINITY;
}

// ---------------- concat [x_enc | u] -----------------------------------------
__global__ void concat_xu(const float* __restrict__ x, const float* __restrict__ u,
                          float* __restrict__ xu)
{
    const size_t total = (size_t)TOK * (DX_ + DU_);
    for (size_t i = (size_t)blockIdx.x * blockDim.x + threadIdx.x; i < total;
         i += (size_t)gridDim.x * blockDim.x) {
        size_t tkn = i / (DX_ + DU_);
        int c = (int)(i - tkn * (DX_ + DU_));
        xu[i] = (c < DX_) ? x[tkn * DX_ + c] : u[tkn * DU_ + (c - DX_)];
    }
}

// ---------------- broadcast query tokens over batch --------------------------
__global__ void bcast_q(const float* __restrict__ qt, float* __restrict__ Q)
{
    const size_t total = (size_t)BPQ * DK_;
    const size_t per = (size_t)PP * DK_;
    for (size_t i = (size_t)blockIdx.x * blockDim.x + threadIdx.x; i < total;
         i += (size_t)gridDim.x * blockDim.x) {
        Q[i] = qt[i % per];
    }
}

// ---------------- host launcher ----------------------------------------------
extern "C" void kernel_launch(void* const* d_in, const int* in_sizes, int n_in,
                              void* d_out, int out_size)
{
    const float* x_enc = (const float*)d_in[0];
    const float* u     = (const float*)d_in[1];
    const void*  mask  = d_in[2];
    const float* sw    = (const float*)d_in[3];
    const float* k_w1 = (const float*)d_in[4];  const float* k_b1 = (const float*)d_in[5];
    const float* k_w2 = (const float*)d_in[6];  const float* k_b2 = (const float*)d_in[7];
    const float* k_w3 = (const float*)d_in[8];  const float* k_b3 = (const float*)d_in[9];
    const float* v_w1 = (const float*)d_in[10]; const float* v_b1 = (const float*)d_in[11];
    const float* v_w2 = (const float*)d_in[12]; const float* v_b2 = (const float*)d_in[13];
    const float* v_w3 = (const float*)d_in[14]; const float* v_b3 = (const float*)d_in[15];
    const float* qtok = (const float*)d_in[16];
    const float* rho_w1 = (const float*)d_in[17]; const float* rho_b1 = (const float*)d_in[18];
    const float* rho_w2 = (const float*)d_in[19]; const float* rho_b2 = (const float*)d_in[20];
    const float* ref_w1 = (const float*)d_in[21]; const float* ref_b1 = (const float*)d_in[22];
    const float* ref_w2 = (const float*)d_in[23]; const float* ref_b2 = (const float*)d_in[24];
    const float* ln_g = (const float*)d_in[25];   const float* ln_b = (const float*)d_in[26];
    float* out = (float*)d_out;

    float *h1, *h2, *Kb, *Vb, *xu, *S, *Q, *pool, *dQ, *lw;
    cudaGetSymbolAddress((void**)&h1, g_h1);
    cudaGetSymbolAddress((void**)&h2, g_h2);
    cudaGetSymbolAddress((void**)&Kb, g_Kb);
    cudaGetSymbolAddress((void**)&Vb, g_Vb);
    cudaGetSymbolAddress((void**)&xu, g_xu);
    cudaGetSymbolAddress((void**)&S,  g_S);
    cudaGetSymbolAddress((void**)&Q,  g_Q);
    cudaGetSymbolAddress((void**)&pool, g_pool);
    cudaGetSymbolAddress((void**)&dQ, g_dQ);
    cudaGetSymbolAddress((void**)&lw, g_lw);

    const float scale = 0.08838834764831843f; // 1/sqrt(128)

    // prep
    prep_logw<<<(TOK + 255) / 256, 256>>>(mask, sw, lw, TOK);
    concat_xu<<<2048, 256>>>(x_enc, u, xu);
    bcast_q<<<2048, 256>>>(qtok, Q);

    // K = mlp3(x_enc):  (TOK,128)->512->512->128
    gemm_tc<2,false><<<dim3(HH/128, TOK/128, 1), 256>>>(x_enc, k_w1, k_b1, h1, HH, DX_, 0.f, 0,0,0,0);
    gemm_tc<2,false><<<dim3(HH/128, TOK/128, 1), 256>>>(h1, k_w2, k_b2, h2, HH, HH, 0.f, 0,0,0,0);
    gemm_tc<1,false><<<dim3(DK_/128, TOK/128, 1), 256>>>(h2, k_w3, k_b3, Kb, DK_, HH, 0.f, 0,0,0,0);

    // V = mlp3([x_enc|u]): (TOK,192)->512->512->128
    gemm_tc<2,false><<<dim3(HH/128, TOK/128, 1), 256>>>(xu, v_w1, v_b1, h1, HH, DX_+DU_, 0.f, 0,0,0,0);
    gemm_tc<2,false><<<dim3(HH/128, TOK/128, 1), 256>>>(h1, v_w2, v_b2, h2, HH, HH, 0.f, 0,0,0,0);
    gemm_tc<1,false><<<dim3(DV_/128, TOK/128, 1), 256>>>(h2, v_w3, v_b3, Vb, DV_, HH, 0.f, 0,0,0,0);

    // attention + refinement (3 iterations)
    for (int iter = 0; iter < 3; iter++) {
        // scores = Q @ K^T * scale + logw   [per batch: 256 x 4096]
        gemm_tc<3,true><<<dim3(NN_/128, PP/128, BB), 256>>>(
            Q, Kb, lw, S, NN_, DK_, scale,
            (size_t)PP*DK_, (size_t)NN_*DK_, (size_t)PP*NN_, (size_t)NN_);
        softmax4096<<<BB*PP, 256>>>(S);
        // pooled = A @ V via split-K (partials into g_h2 scratch)
        gemm_avk_tc<<<dim3(1, PP/128, BB*KSPLIT), 256>>>(S, Vb, h2);
        reduce_avk<<<(BB*PP*DV_ + 255)/256, 256>>>(h2, pool);
        if (iter < 2) {
            gemm_tc<2,false><<<dim3(HH/128, BPQ/128, 1), 256>>>(pool, ref_w1, ref_b1, h1, HH, DV_, 0.f, 0,0,0,0);
            gemm_tc<1,false><<<dim3(DK_/128, BPQ/128, 1), 256>>>(h1, ref_w2, ref_b2, dQ, DK_, HH, 0.f, 0,0,0,0);
            add_layernorm<<<BPQ, 128>>>(Q, dQ, ln_g, ln_b);
        }
    }

    // out = mlp2(pooled): (8192,128)->512->256
    gemm_tc<2,false><<<dim3(HH/128, BPQ/128, 1), 256>>>(pool, rho_w1, rho_b1, h1, HH, DV_, 0.f, 0,0,0,0);
    gemm_tc<1,false><<<dim3(DOUT_/128, BPQ/128, 1), 256>>>(h1, rho_w2, rho_b2, out, DOUT_, HH, 0.f, 0,0,0,0);

    (void)in_sizes; (void)n_in; (void)out_size;
}